// round 5
// baseline (speedup 1.0000x reference)
#include <cuda_runtime.h>
#include <math.h>

// ---------------- fixed problem dimensions ----------------
#define Bb      4
#define Ss      2048
#define HIDDEN  512
#define Hh      8
#define HD      64
#define CHK     64
#define NCHK    32          // Ss / CHK
#define BHN     32          // Bb * Hh
#define MROWS   8192        // Bb * Ss
#define NQKV    2048        // 4 * HIDDEN  (Q|K|V|G packed columns)

// ---------------- device scratch (no runtime allocation allowed) ----------------
__device__ float g_Wpack[HIDDEN * NQKV];     // [k][j] packed weights, 4 MB
__device__ float g_Q[BHN * Ss * HD];         // [bh][s][d]
__device__ float g_K[BHN * Ss * HD];
__device__ float g_V[BHN * Ss * HD];
__device__ float g_gate[MROWS * HIDDEN];
__device__ float g_Y[BHN * Ss * HD];
__device__ float g_Z[MROWS * HIDDEN];
__device__ float g_sq[Ss * 32];              // sin*scale   (for Q)
__device__ float g_cq[Ss * 32];              // cos*scale
__device__ float g_sk[Ss * 32];              // sin/scale   (for K)
__device__ float g_ck[Ss * 32];              // cos/scale

// ---------------- pack W_Q|W_K|W_V|W_G into one [512 x 2048] B matrix ----------------
__global__ void pack_w(const float* __restrict__ WQ, const float* __restrict__ WK,
                       const float* __restrict__ WV, const float* __restrict__ WG) {
    int idx = blockIdx.x * blockDim.x + threadIdx.x;     // over 512*2048
    if (idx >= HIDDEN * NQKV) return;
    int k = idx / NQKV, j = idx - k * NQKV;
    int t = j >> 9;            // 0:Q 1:K 2:V 3:G
    int c = j & 511;
    int n = c >> 6, d = c & 63;
    float v;
    if (t == 0)      v = WQ[(n * HIDDEN + k) * HD + d];
    else if (t == 1) v = WK[(n * HIDDEN + k) * HD + d];
    else if (t == 2) v = WV[(n * HIDDEN + k) * HD + d];
    else             v = WG[k * HIDDEN + c];
    g_Wpack[k * NQKV + j] = v;
}

// ---------------- xPos factor tables (double precision, fp32-rounding mimicry) ----------------
__global__ void xpos_tables() {
    int idx = blockIdx.x * blockDim.x + threadIdx.x;     // Ss * 32
    if (idx >= Ss * 32) return;
    int pos = idx >> 5, t = idx & 31;
    // inv_freq = 1/10000^(t/32) as f32, ang = pos*inv_freq rounded to f32 (like reference)
    float inv_freq = (float)pow(10000.0, -(double)t / 32.0);
    float ang_f = (float)((double)pos * (double)inv_freq);
    double sn = sin((double)ang_f);
    double cs = cos((double)ang_f);
    float sbase = ((float)(2 * t) + 25.6f) / 89.6f;      // (2t + 0.4*64)/(1.4*64)
    float scf = (float)pow((double)sbase, (double)pos / 512.0);
    float snf = (float)sn, csf = (float)cs;
    g_sq[idx] = snf * scf;
    g_cq[idx] = csf * scf;
    float iscf = 1.0f / scf;
    g_sk[idx] = snf * iscf;
    g_ck[idx] = csf * iscf;
}

// ---------------- fused QKV+gate projection GEMM: C = X @ Wpack, 128x128x16 tiles ----------------
__global__ __launch_bounds__(256) void gemm_proj(const float* __restrict__ X) {
    __shared__ float As[16][132];   // A^T: As[k][m]
    __shared__ float Bs[16][132];
    const int tid = threadIdx.x;
    const int tx = tid & 15, ty = tid >> 4;
    const int rowA = blockIdx.y * 128;
    const int colB = blockIdx.x * 128;
    float acc[8][8];
#pragma unroll
    for (int a = 0; a < 8; a++)
#pragma unroll
        for (int b = 0; b < 8; b++) acc[a][b] = 0.f;

    for (int k0 = 0; k0 < HIDDEN; k0 += 16) {
#pragma unroll
        for (int u = 0; u < 2; u++) {
            int fi = u * 256 + tid;                 // 0..511 float4 units
            int m  = fi >> 2;                       // 0..127
            int kk = (fi & 3) << 2;                 // 0,4,8,12
            float4 va = *(const float4*)(X + (rowA + m) * HIDDEN + k0 + kk);
            As[kk + 0][m] = va.x; As[kk + 1][m] = va.y;
            As[kk + 2][m] = va.z; As[kk + 3][m] = va.w;
            int kb = fi >> 5;                       // 0..15
            int c4 = (fi & 31) << 2;                // 0..124
            *(float4*)&Bs[kb][c4] = *(const float4*)(g_Wpack + (k0 + kb) * NQKV + colB + c4);
        }
        __syncthreads();
#pragma unroll
        for (int k = 0; k < 16; k++) {
            float ar[8], br[8];
            *(float4*)(ar)     = *(float4*)&As[k][ty * 8];
            *(float4*)(ar + 4) = *(float4*)&As[k][ty * 8 + 4];
            *(float4*)(br)     = *(float4*)&Bs[k][tx * 8];
            *(float4*)(br + 4) = *(float4*)&Bs[k][tx * 8 + 4];
#pragma unroll
            for (int a = 0; a < 8; a++)
#pragma unroll
                for (int b = 0; b < 8; b++) acc[a][b] += ar[a] * br[b];
        }
        __syncthreads();
    }

    // epilogue: route by column type; whole 8-col group lies in one (t, head) block
    const int c0 = colB + tx * 8;
    const int t  = c0 >> 9;
    const int cc = c0 & 511;
    const int hh = cc >> 6;
    const int d0 = cc & 63;
#pragma unroll
    for (int a = 0; a < 8; a++) {
        int r  = rowA + ty * 8 + a;
        int bb = r >> 11;       // / 2048
        int s  = r & 2047;
        if (t <= 1) {
            const float* stab = (t == 0) ? g_sq : g_sk;
            const float* ctab = (t == 0) ? g_cq : g_ck;
            float o[8];
#pragma unroll
            for (int p = 0; p < 4; p++) {
                int ti = s * 32 + (d0 >> 1) + p;
                float sn = stab[ti], csn = ctab[ti];
                float x0 = acc[a][2 * p], x1 = acc[a][2 * p + 1];
                o[2 * p]     = x0 * csn - x1 * sn;
                o[2 * p + 1] = x1 * csn + x0 * sn;
            }
            float* dst = ((t == 0) ? g_Q : g_K) + ((bb * Hh + hh) * Ss + s) * HD + d0;
#pragma unroll
            for (int q = 0; q < 8; q++) dst[q] = o[q];
        } else if (t == 2) {
            float* dst = g_V + ((bb * Hh + hh) * Ss + s) * HD + d0;
#pragma unroll
            for (int q = 0; q < 8; q++) dst[q] = acc[a][q];
        } else {
            float* dst = g_gate + r * HIDDEN + cc;
#pragma unroll
            for (int q = 0; q < 8; q++) {
                float xv = acc[a][q];
                dst[q] = xv / (1.f + expf(-xv));    // silu
            }
        }
    }
}

// ---------------- retention: per (bh, qchunk) block, loop key chunks with decay ----------------
#define RET_SMEM_FLOATS (3 * 64 * 68 + 128)
#define RET_SMEM_BYTES  (RET_SMEM_FLOATS * 4)

__global__ __launch_bounds__(256) void retention() {
    extern __shared__ float sm[];
    float* Qt   = sm;                 // [d][i], stride 68
    float* Kt   = sm + 64 * 68;       // [d][j], stride 68; reused as St[j][i]
    float* Vs   = sm + 2 * 64 * 68;   // [j][n], stride 68
    float* gpos = sm + 3 * 64 * 68;   // gamma^i, 64
    float* gneg = gpos + 64;          // gamma^-j, 64

    const int qc = blockIdx.x;
    const int bh = blockIdx.y;
    const int h  = bh & 7;
    const int tid = threadIdx.x;
    const int tx = tid & 15, ty = tid >> 4;
    const int i0 = ty * 4, j0 = tx * 4;
    const int rr = tid >> 2;          // 0..63 row for tile loads
    const int g4 = (tid & 3) * 4;     // col group base (add 16*u)

    // gamma, mimicking the reference's f32 linspace/exp path
    float lg0 = logf(1.0f / 32.0f);
    float lg1 = logf(1.0f / 512.0f);
    float lin = lg0 + (float)h * ((lg1 - lg0) / 7.0f);
    float gamma = 1.0f - expf(lin);
    double gd = (double)gamma;
    if (tid < 64)       gpos[tid]      = (float)pow(gd, (double)tid);
    else if (tid < 128) gneg[tid - 64] = (float)pow(gd, -(double)(tid - 64));

    // load Q tile transposed (Qt[d][i])
    const float* Qg = g_Q + (bh * Ss + qc * CHK) * HD;
#pragma unroll
    for (int u = 0; u < 4; u++) {
        int c4 = g4 + u * 16;
        float4 v = *(const float4*)(Qg + rr * HD + c4);
        Qt[(c4 + 0) * 68 + rr] = v.x;
        Qt[(c4 + 1) * 68 + rr] = v.y;
        Qt[(c4 + 2) * 68 + rr] = v.z;
        Qt[(c4 + 3) * 68 + rr] = v.w;
    }

    float o[4][4];
#pragma unroll
    for (int a = 0; a < 4; a++)
#pragma unroll
        for (int b = 0; b < 4; b++) o[a][b] = 0.f;

    for (int kc = qc; kc >= 0; --kc) {
        int dlt = qc - kc;
        float cross = 1.0f;
        if (dlt) {
            double cd = pow(gd, 64.0 * (double)dlt);
            if (cd < 1e-10) break;   // contributions < 1e-9 relative; uniform across block
            cross = (float)cd;
        }
        __syncthreads();             // previous stage B done with Kt/Vs
        const float* Kg = g_K + (bh * Ss + kc * CHK) * HD;
        const float* Vg = g_V + (bh * Ss + kc * CHK) * HD;
#pragma unroll
        for (int u = 0; u < 4; u++) {
            int c4 = g4 + u * 16;
            float4 v = *(const float4*)(Kg + rr * HD + c4);
            Kt[(c4 + 0) * 68 + rr] = v.x;
            Kt[(c4 + 1) * 68 + rr] = v.y;
            Kt[(c4 + 2) * 68 + rr] = v.z;
            Kt[(c4 + 3) * 68 + rr] = v.w;
            *(float4*)(Vs + rr * 68 + c4) = *(const float4*)(Vg + rr * HD + c4);
        }
        __syncthreads();

        // stage A: S = Q @ K^T   (each thread 4x4)
        float sv[4][4];
#pragma unroll
        for (int a = 0; a < 4; a++)
#pragma unroll
            for (int b = 0; b < 4; b++) sv[a][b] = 0.f;
#pragma unroll 8
        for (int d = 0; d < 64; d++) {
            float4 qa = *(float4*)(Qt + d * 68 + i0);
            float4 kb = *(float4*)(Kt + d * 68 + j0);
            float aq[4] = {qa.x, qa.y, qa.z, qa.w};
            float bk[4] = {kb.x, kb.y, kb.z, kb.w};
#pragma unroll
            for (int a = 0; a < 4; a++)
#pragma unroll
                for (int b = 0; b < 4; b++) sv[a][b] += aq[a] * bk[b];
        }

        // decay multiply
        if (dlt == 0) {
#pragma unroll
            for (int a = 0; a < 4; a++)
#pragma unroll
                for (int b = 0; b < 4; b++) {
                    int e = (i0 + a) - (j0 + b);
                    if (e < 0) e = -e;
                    sv[a][b] *= gpos[e];
                }
        } else {
#pragma unroll
            for (int a = 0; a < 4; a++) {
                float fa = cross * gpos[i0 + a];
#pragma unroll
                for (int b = 0; b < 4; b++) sv[a][b] *= fa * gneg[j0 + b];
            }
        }
        __syncthreads();             // all threads done reading Kt before overwrite

        // store S transposed into Kt buffer: St[j][i]
#pragma unroll
        for (int b = 0; b < 4; b++) {
            *(float4*)(Kt + (j0 + b) * 68 + i0) =
                make_float4(sv[0][b], sv[1][b], sv[2][b], sv[3][b]);
        }
        __syncthreads();

        // stage B: O += S @ V
#pragma unroll 8
        for (int j = 0; j < 64; j++) {
            float4 s4 = *(float4*)(Kt + j * 68 + i0);
            float4 vv = *(float4*)(Vs + j * 68 + j0);
            float as[4] = {s4.x, s4.y, s4.z, s4.w};
            float bv[4] = {vv.x, vv.y, vv.z, vv.w};
#pragma unroll
            for (int a = 0; a < 4; a++)
#pragma unroll
                for (int b = 0; b < 4; b++) o[a][b] += as[a] * bv[b];
        }
    }

    float* Yg = g_Y + (bh * Ss + qc * CHK) * HD;
#pragma unroll
    for (int a = 0; a < 4; a++)
        *(float4*)(Yg + (i0 + a) * HD + j0) = make_float4(o[a][0], o[a][1], o[a][2], o[a][3]);
}

// ---------------- per-head groupnorm + gate multiply ----------------
__global__ __launch_bounds__(256) void gn_gate(const float* __restrict__ gnw,
                                               const float* __restrict__ gnb) {
    int s = blockIdx.x, b = blockIdx.y;
    int tid = threadIdx.x;
    int h = tid >> 5, lane = tid & 31;
    const float* Yg = g_Y + ((b * Hh + h) * Ss + s) * HD;
    float y0 = Yg[lane], y1 = Yg[lane + 32];
    float sum = y0 + y1, sq = y0 * y0 + y1 * y1;
#pragma unroll
    for (int off = 16; off; off >>= 1) {
        sum += __shfl_xor_sync(0xffffffffu, sum, off);
        sq  += __shfl_xor_sync(0xffffffffu, sq,  off);
    }
    float mu = sum * (1.f / 64.f);
    float var = sq * (1.f / 64.f) - mu * mu;
    float rstd = rsqrtf(var + 1e-5f);
    int r = b * Ss + s;
    int c0 = h * 64 + lane;
    float z0 = (y0 - mu) * rstd * gnw[c0]      + gnb[c0];
    float z1 = (y1 - mu) * rstd * gnw[c0 + 32] + gnb[c0 + 32];
    g_Z[r * HIDDEN + c0]      = z0 * g_gate[r * HIDDEN + c0];
    g_Z[r * HIDDEN + c0 + 32] = z1 * g_gate[r * HIDDEN + c0 + 32];
}

// ---------------- output GEMM: out = Z @ W_O, 128x128x16 tiles ----------------
__global__ __launch_bounds__(256) void gemm_out(const float* __restrict__ WO,
                                                float* __restrict__ out) {
    __shared__ float As[16][132];
    __shared__ float Bs[16][132];
    const int tid = threadIdx.x;
    const int tx = tid & 15, ty = tid >> 4;
    const int rowA = blockIdx.y * 128;
    const int colB = blockIdx.x * 128;
    float acc[8][8];
#pragma unroll
    for (int a = 0; a < 8; a++)
#pragma unroll
        for (int b = 0; b < 8; b++) acc[a][b] = 0.f;

    for (int k0 = 0; k0 < HIDDEN; k0 += 16) {
#pragma unroll
        for (int u = 0; u < 2; u++) {
            int fi = u * 256 + tid;
            int m  = fi >> 2;
            int kk = (fi & 3) << 2;
            float4 va = *(const float4*)(g_Z + (rowA + m) * HIDDEN + k0 + kk);
            As[kk + 0][m] = va.x; As[kk + 1][m] = va.y;
            As[kk + 2][m] = va.z; As[kk + 3][m] = va.w;
            int kb = fi >> 5;
            int c4 = (fi & 31) << 2;
            *(float4*)&Bs[kb][c4] = *(const float4*)(WO + (k0 + kb) * HIDDEN + colB + c4);
        }
        __syncthreads();
#pragma unroll
        for (int k = 0; k < 16; k++) {
            float ar[8], br[8];
            *(float4*)(ar)     = *(float4*)&As[k][ty * 8];
            *(float4*)(ar + 4) = *(float4*)&As[k][ty * 8 + 4];
            *(float4*)(br)     = *(float4*)&Bs[k][tx * 8];
            *(float4*)(br + 4) = *(float4*)&Bs[k][tx * 8 + 4];
#pragma unroll
            for (int a = 0; a < 8; a++)
#pragma unroll
                for (int b = 0; b < 8; b++) acc[a][b] += ar[a] * br[b];
        }
        __syncthreads();
    }
#pragma unroll
    for (int a = 0; a < 8; a++) {
        int r = rowA + ty * 8 + a;
        float* dst = out + r * HIDDEN + colB + tx * 8;
#pragma unroll
        for (int q = 0; q < 8; q++) dst[q] = acc[a][q];
    }
}

// ---------------- launcher ----------------
extern "C" void kernel_launch(void* const* d_in, const int* in_sizes, int n_in,
                              void* d_out, int out_size) {
    const float* X   = (const float*)d_in[0];
    const float* WQ  = (const float*)d_in[1];
    const float* WK  = (const float*)d_in[2];
    const float* WV  = (const float*)d_in[3];
    const float* WG  = (const float*)d_in[4];
    const float* WO  = (const float*)d_in[5];
    const float* gnw = (const float*)d_in[6];
    const float* gnb = (const float*)d_in[7];
    float* out = (float*)d_out;
    (void)in_sizes; (void)n_in; (void)out_size;

    cudaFuncSetAttribute(retention, cudaFuncAttributeMaxDynamicSharedMemorySize, RET_SMEM_BYTES);

    pack_w<<<(HIDDEN * NQKV + 255) / 256, 256>>>(WQ, WK, WV, WG);
    xpos_tables<<<(Ss * 32 + 255) / 256, 256>>>();
    gemm_proj<<<dim3(NQKV / 128, MROWS / 128), 256>>>(X);
    retention<<<dim3(NCHK, BHN), 256, RET_SMEM_BYTES>>>();
    gn_gate<<<dim3(Ss, Bb), 256>>>(gnw, gnb);
    gemm_out<<<dim3(HIDDEN / 128, MROWS / 128), 256>>>(WO, out);
}

// round 6
// speedup vs baseline: 2.4923x; 2.4923x over previous
#include <cuda_runtime.h>
#include <math.h>

// ---------------- fixed problem dimensions ----------------
#define Bb      4
#define Ss      2048
#define HIDDEN  512
#define Hh      8
#define HD      64
#define CHK     64
#define NCHK    32          // Ss / CHK
#define BHN     32          // Bb * Hh
#define MROWS   8192        // Bb * Ss
#define NQKV    2048        // 4 * HIDDEN  (Q|K|V|G packed columns)

// ---------------- device scratch (no runtime allocation allowed) ----------------
__device__ float g_Wpack[HIDDEN * NQKV];     // [k][j] packed weights, 4 MB
__device__ float g_Q[BHN * Ss * HD];         // [bh][s][d]
__device__ float g_K[BHN * Ss * HD];
__device__ float g_V[BHN * Ss * HD];
__device__ float g_gate[MROWS * HIDDEN];
__device__ float g_Y[BHN * Ss * HD];         // intra-chunk output
__device__ float g_Y2[BHN * Ss * HD];        // cross-chunk output
__device__ float g_Z[MROWS * HIDDEN];
__device__ float g_sq[Ss * 32];              // sin*scale   (for Q)
__device__ float g_cq[Ss * 32];              // cos*scale
__device__ float g_sk[Ss * 32];              // sin/scale   (for K)
__device__ float g_ck[Ss * 32];              // cos/scale

// ---------------- pack W_Q|W_K|W_V|W_G into one [512 x 2048] B matrix ----------------
__global__ void pack_w(const float* __restrict__ WQ, const float* __restrict__ WK,
                       const float* __restrict__ WV, const float* __restrict__ WG) {
    int idx = blockIdx.x * blockDim.x + threadIdx.x;     // over 512*2048
    if (idx >= HIDDEN * NQKV) return;
    int k = idx / NQKV, j = idx - k * NQKV;
    int t = j >> 9;            // 0:Q 1:K 2:V 3:G
    int c = j & 511;
    int n = c >> 6, d = c & 63;
    float v;
    if (t == 0)      v = WQ[(n * HIDDEN + k) * HD + d];
    else if (t == 1) v = WK[(n * HIDDEN + k) * HD + d];
    else if (t == 2) v = WV[(n * HIDDEN + k) * HD + d];
    else             v = WG[k * HIDDEN + c];
    g_Wpack[k * NQKV + j] = v;
}

// ---------------- xPos factor tables (double precision, fp32-rounding mimicry) ----------------
__global__ void xpos_tables() {
    int idx = blockIdx.x * blockDim.x + threadIdx.x;     // Ss * 32
    if (idx >= Ss * 32) return;
    int pos = idx >> 5, t = idx & 31;
    float inv_freq = (float)pow(10000.0, -(double)t / 32.0);
    float ang_f = (float)((double)pos * (double)inv_freq);
    double sn = sin((double)ang_f);
    double cs = cos((double)ang_f);
    float sbase = ((float)(2 * t) + 25.6f) / 89.6f;      // (2t + 0.4*64)/(1.4*64)
    float scf = (float)pow((double)sbase, (double)pos / 512.0);
    float snf = (float)sn, csf = (float)cs;
    g_sq[idx] = snf * scf;
    g_cq[idx] = csf * scf;
    float iscf = 1.0f / scf;
    g_sk[idx] = snf * iscf;
    g_ck[idx] = csf * iscf;
}

// ---------------- fused QKV+gate projection GEMM: C = X @ Wpack, 128x128x16 tiles ----------------
// register-prefetch double buffering of the k-slab
__global__ __launch_bounds__(256, 2) void gemm_proj(const float* __restrict__ X) {
    __shared__ float As[16][132];   // A^T: As[k][m]
    __shared__ float Bs[16][132];
    const int tid = threadIdx.x;
    const int tx = tid & 15, ty = tid >> 4;
    const int rowA = blockIdx.y * 128;
    const int colB = blockIdx.x * 128;
    float acc[8][8];
#pragma unroll
    for (int a = 0; a < 8; a++)
#pragma unroll
        for (int b = 0; b < 8; b++) acc[a][b] = 0.f;

    // staging coordinates (u = 0,1 handled via fixed offsets)
    const int am  = tid >> 2;            // 0..63
    const int akk = (tid & 3) << 2;      // 0,4,8,12
    const int bk  = tid >> 5;            // 0..7
    const int bc4 = (tid & 31) << 2;     // 0..124
    const float* Aptr = X + (rowA + am) * HIDDEN + akk;
    const float* Bptr = g_Wpack + bk * NQKV + colB + bc4;

    float4 pa[2], pb[2];
    pa[0] = *(const float4*)(Aptr);
    pa[1] = *(const float4*)(Aptr + 64 * HIDDEN);
    pb[0] = *(const float4*)(Bptr);
    pb[1] = *(const float4*)(Bptr + 8 * NQKV);

    for (int k0 = 0; k0 < HIDDEN; k0 += 16) {
#pragma unroll
        for (int u = 0; u < 2; u++) {
            int m = u * 64 + am;
            As[akk + 0][m] = pa[u].x; As[akk + 1][m] = pa[u].y;
            As[akk + 2][m] = pa[u].z; As[akk + 3][m] = pa[u].w;
            *(float4*)&Bs[u * 8 + bk][bc4] = pb[u];
        }
        __syncthreads();
        if (k0 + 16 < HIDDEN) {
            pa[0] = *(const float4*)(Aptr + k0 + 16);
            pa[1] = *(const float4*)(Aptr + 64 * HIDDEN + k0 + 16);
            pb[0] = *(const float4*)(Bptr + (k0 + 16) * NQKV);
            pb[1] = *(const float4*)(Bptr + (k0 + 24) * NQKV);
        }
#pragma unroll
        for (int k = 0; k < 16; k++) {
            float ar[8], br[8];
            *(float4*)(ar)     = *(float4*)&As[k][ty * 8];
            *(float4*)(ar + 4) = *(float4*)&As[k][ty * 8 + 4];
            *(float4*)(br)     = *(float4*)&Bs[k][tx * 8];
            *(float4*)(br + 4) = *(float4*)&Bs[k][tx * 8 + 4];
#pragma unroll
            for (int a = 0; a < 8; a++)
#pragma unroll
                for (int b = 0; b < 8; b++) acc[a][b] += ar[a] * br[b];
        }
        __syncthreads();
    }

    // epilogue: route by column type; whole 8-col group lies in one (t, head) block
    const int c0 = colB + tx * 8;
    const int t  = c0 >> 9;
    const int cc = c0 & 511;
    const int hh = cc >> 6;
    const int d0 = cc & 63;
#pragma unroll
    for (int a = 0; a < 8; a++) {
        int r  = rowA + ty * 8 + a;
        int bb = r >> 11;       // / 2048
        int s  = r & 2047;
        if (t <= 1) {
            const float* stab = (t == 0) ? g_sq : g_sk;
            const float* ctab = (t == 0) ? g_cq : g_ck;
            float o[8];
#pragma unroll
            for (int p = 0; p < 4; p++) {
                int ti = s * 32 + (d0 >> 1) + p;
                float sn = stab[ti], csn = ctab[ti];
                float x0 = acc[a][2 * p], x1 = acc[a][2 * p + 1];
                o[2 * p]     = x0 * csn - x1 * sn;
                o[2 * p + 1] = x1 * csn + x0 * sn;
            }
            float* dst = ((t == 0) ? g_Q : g_K) + ((bb * Hh + hh) * Ss + s) * HD + d0;
#pragma unroll
            for (int q = 0; q < 8; q++) dst[q] = o[q];
        } else if (t == 2) {
            float* dst = g_V + ((bb * Hh + hh) * Ss + s) * HD + d0;
#pragma unroll
            for (int q = 0; q < 8; q++) dst[q] = acc[a][q];
        } else {
            float* dst = g_gate + r * HIDDEN + cc;
#pragma unroll
            for (int q = 0; q < 8; q++) {
                float xv = acc[a][q];
                dst[q] = xv / (1.f + expf(-xv));    // silu
            }
        }
    }
}

// ---------------- retention intra: diagonal chunk only (fully parallel) ----------------
#define RET_SMEM_FLOATS (3 * 64 * 68 + 128)
#define RET_SMEM_BYTES  (RET_SMEM_FLOATS * 4)

__global__ __launch_bounds__(256) void retention_intra() {
    extern __shared__ float sm[];
    float* Qt   = sm;                 // [d][i], stride 68
    float* Kt   = sm + 64 * 68;       // [d][j], stride 68; reused as St[j][i]
    float* Vs   = sm + 2 * 64 * 68;   // [j][n], stride 68
    float* gpos = sm + 3 * 64 * 68;   // gamma^e, 64

    const int qc = blockIdx.x;
    const int bh = blockIdx.y;
    const int h  = bh & 7;
    const int tid = threadIdx.x;
    const int tx = tid & 15, ty = tid >> 4;
    const int i0 = ty * 4, j0 = tx * 4;
    const int rr = tid >> 2;          // 0..63 row for tile loads
    const int g4 = (tid & 3) * 4;     // col group base (add 16*u)

    float lg0 = logf(1.0f / 32.0f);
    float lg1 = logf(1.0f / 512.0f);
    float lin = lg0 + (float)h * ((lg1 - lg0) / 7.0f);
    float gamma = 1.0f - expf(lin);
    double gd = (double)gamma;
    if (tid < 64) gpos[tid] = (float)pow(gd, (double)tid);

    const float* Qg = g_Q + (bh * Ss + qc * CHK) * HD;
    const float* Kg = g_K + (bh * Ss + qc * CHK) * HD;
    const float* Vg = g_V + (bh * Ss + qc * CHK) * HD;
#pragma unroll
    for (int u = 0; u < 4; u++) {
        int c4 = g4 + u * 16;
        float4 q = *(const float4*)(Qg + rr * HD + c4);
        Qt[(c4 + 0) * 68 + rr] = q.x;
        Qt[(c4 + 1) * 68 + rr] = q.y;
        Qt[(c4 + 2) * 68 + rr] = q.z;
        Qt[(c4 + 3) * 68 + rr] = q.w;
        float4 k = *(const float4*)(Kg + rr * HD + c4);
        Kt[(c4 + 0) * 68 + rr] = k.x;
        Kt[(c4 + 1) * 68 + rr] = k.y;
        Kt[(c4 + 2) * 68 + rr] = k.z;
        Kt[(c4 + 3) * 68 + rr] = k.w;
        *(float4*)(Vs + rr * 68 + c4) = *(const float4*)(Vg + rr * HD + c4);
    }
    __syncthreads();

    // S = Q @ K^T
    float sv[4][4];
#pragma unroll
    for (int a = 0; a < 4; a++)
#pragma unroll
        for (int b = 0; b < 4; b++) sv[a][b] = 0.f;
#pragma unroll 8
    for (int d = 0; d < 64; d++) {
        float4 qa = *(float4*)(Qt + d * 68 + i0);
        float4 kb = *(float4*)(Kt + d * 68 + j0);
        float aq[4] = {qa.x, qa.y, qa.z, qa.w};
        float bk2[4] = {kb.x, kb.y, kb.z, kb.w};
#pragma unroll
        for (int a = 0; a < 4; a++)
#pragma unroll
            for (int b = 0; b < 4; b++) sv[a][b] += aq[a] * bk2[b];
    }
    // decay: gamma^|i-j|
#pragma unroll
    for (int a = 0; a < 4; a++)
#pragma unroll
        for (int b = 0; b < 4; b++) {
            int e = (i0 + a) - (j0 + b);
            if (e < 0) e = -e;
            sv[a][b] *= gpos[e];
        }
    __syncthreads();
    // store S transposed into Kt buffer: St[j][i]
#pragma unroll
    for (int b = 0; b < 4; b++) {
        *(float4*)(Kt + (j0 + b) * 68 + i0) =
            make_float4(sv[0][b], sv[1][b], sv[2][b], sv[3][b]);
    }
    __syncthreads();

    // O = S @ V
    float o[4][4];
#pragma unroll
    for (int a = 0; a < 4; a++)
#pragma unroll
        for (int b = 0; b < 4; b++) o[a][b] = 0.f;
#pragma unroll 8
    for (int j = 0; j < 64; j++) {
        float4 s4 = *(float4*)(Kt + j * 68 + i0);
        float4 vv = *(float4*)(Vs + j * 68 + j0);
        float as[4] = {s4.x, s4.y, s4.z, s4.w};
        float bv[4] = {vv.x, vv.y, vv.z, vv.w};
#pragma unroll
        for (int a = 0; a < 4; a++)
#pragma unroll
            for (int b = 0; b < 4; b++) o[a][b] += as[a] * bv[b];
    }

    float* Yg = g_Y + (bh * Ss + qc * CHK) * HD;
#pragma unroll
    for (int a = 0; a < 4; a++)
        *(float4*)(Yg + (i0 + a) * HD + j0) = make_float4(o[a][0], o[a][1], o[a][2], o[a][3]);
}

// ---------------- retention cross: chunked recurrence over state R[d][n] ----------------
// grid.x = BHN*4 : (bh, quarter of V columns). 32 sequential chunk steps.
// O_cross[i,n] = gamma^i * Q[i,:] @ R ;  R <- gamma^64 * (R + (gamma^-j K)^T V)
__global__ __launch_bounds__(256) void retention_cross() {
    __shared__ float Qt[64 * 68];   // [d][i], Q row i pre-scaled by gamma^i
    __shared__ float Ks[64 * 68];   // [j][d], K row j pre-scaled by gamma^-j
    __shared__ float Vs[64 * 20];   // [j][n] quarter (16 cols)
    __shared__ float Rs[64 * 20];   // state [d][n]

    const int bh  = blockIdx.x >> 2;
    const int qtr = blockIdx.x & 3;
    const int h   = bh & 7;
    const int tid = threadIdx.x;
    const int tx  = tid & 15, ty = tid >> 4;
    const int i0  = ty * 4;           // m/d tile base for GEMMs
    const int rr  = tid >> 2;         // staging row 0..63
    const int g4  = (tid & 3) * 4;    // staging col group

    float lg0 = logf(1.0f / 32.0f);
    float lg1 = logf(1.0f / 512.0f);
    float lin = lg0 + (float)h * ((lg1 - lg0) / 7.0f);
    float gamma = 1.0f - expf(lin);
    double gd = (double)gamma;
    const float g64f = (float)pow(gd, 64.0);
    const float gq = (float)pow(gd, (double)rr);    // gamma^i for staged Q row
    const float gk = (float)pow(gd, -(double)rr);   // gamma^-j for staged K row

    for (int idx = tid; idx < 64 * 20; idx += 256) Rs[idx] = 0.f;

    const float* Qb = g_Q + bh * Ss * HD;
    const float* Kb = g_K + bh * Ss * HD;
    const float* Vb = g_V + bh * Ss * HD;
    float* Yb = g_Y2 + bh * Ss * HD;
    __syncthreads();

    for (int qc = 0; qc < NCHK; qc++) {
        const float* Qg = Qb + qc * CHK * HD;
        const float* Kg = Kb + qc * CHK * HD;
        const float* Vg = Vb + qc * CHK * HD;
#pragma unroll
        for (int u = 0; u < 4; u++) {
            int c4 = g4 + u * 16;
            float4 q = *(const float4*)(Qg + rr * HD + c4);
            Qt[(c4 + 0) * 68 + rr] = q.x * gq;
            Qt[(c4 + 1) * 68 + rr] = q.y * gq;
            Qt[(c4 + 2) * 68 + rr] = q.z * gq;
            Qt[(c4 + 3) * 68 + rr] = q.w * gq;
            float4 k = *(const float4*)(Kg + rr * HD + c4);
            *(float4*)(Ks + rr * 68 + c4) =
                make_float4(k.x * gk, k.y * gk, k.z * gk, k.w * gk);
        }
        *(float4*)(Vs + rr * 20 + g4) = *(const float4*)(Vg + rr * HD + qtr * 16 + g4);
        __syncthreads();

        // O[i0..i0+3][tx] = sum_d Qt[d][i] * Rs[d][tx]
        float o4[4] = {0.f, 0.f, 0.f, 0.f};
#pragma unroll 8
        for (int d = 0; d < 64; d++) {
            float4 q = *(float4*)(Qt + d * 68 + i0);
            float r = Rs[d * 20 + tx];
            o4[0] += q.x * r; o4[1] += q.y * r; o4[2] += q.z * r; o4[3] += q.w * r;
        }
        float* Yo = Yb + (qc * CHK + i0) * HD + qtr * 16 + tx;
        Yo[0]      = o4[0];
        Yo[HD]     = o4[1];
        Yo[2 * HD] = o4[2];
        Yo[3 * HD] = o4[3];

        // C[i0..i0+3][tx] = sum_j Ks[j][d] * Vs[j][tx]
        float c4a[4] = {0.f, 0.f, 0.f, 0.f};
#pragma unroll 8
        for (int j = 0; j < 64; j++) {
            float4 kk = *(float4*)(Ks + j * 68 + i0);
            float v = Vs[j * 20 + tx];
            c4a[0] += kk.x * v; c4a[1] += kk.y * v; c4a[2] += kk.z * v; c4a[3] += kk.w * v;
        }
        __syncthreads();   // all R reads (GEMM1) done before update
#pragma unroll
        for (int a = 0; a < 4; a++) {
            int off = (i0 + a) * 20 + tx;
            Rs[off] = g64f * (Rs[off] + c4a[a]);
        }
        __syncthreads();   // R updated + tiles free before next staging
    }
}

// ---------------- per-head groupnorm + gate multiply (Y = intra + cross) ----------------
__global__ __launch_bounds__(256) void gn_gate(const float* __restrict__ gnw,
                                               const float* __restrict__ gnb) {
    int s = blockIdx.x, b = blockIdx.y;
    int tid = threadIdx.x;
    int h = tid >> 5, lane = tid & 31;
    const float* Yg  = g_Y  + ((b * Hh + h) * Ss + s) * HD;
    const float* Y2g = g_Y2 + ((b * Hh + h) * Ss + s) * HD;
    float y0 = Yg[lane]      + Y2g[lane];
    float y1 = Yg[lane + 32] + Y2g[lane + 32];
    float sum = y0 + y1, sq = y0 * y0 + y1 * y1;
#pragma unroll
    for (int off = 16; off; off >>= 1) {
        sum += __shfl_xor_sync(0xffffffffu, sum, off);
        sq  += __shfl_xor_sync(0xffffffffu, sq,  off);
    }
    float mu = sum * (1.f / 64.f);
    float var = sq * (1.f / 64.f) - mu * mu;
    float rstd = rsqrtf(var + 1e-5f);
    int r = b * Ss + s;
    int c0 = h * 64 + lane;
    float z0 = (y0 - mu) * rstd * gnw[c0]      + gnb[c0];
    float z1 = (y1 - mu) * rstd * gnw[c0 + 32] + gnb[c0 + 32];
    g_Z[r * HIDDEN + c0]      = z0 * g_gate[r * HIDDEN + c0];
    g_Z[r * HIDDEN + c0 + 32] = z1 * g_gate[r * HIDDEN + c0 + 32];
}

// ---------------- output GEMM: out = Z @ W_O, 128x128x16 tiles, prefetched ----------------
__global__ __launch_bounds__(256, 2) void gemm_out(const float* __restrict__ WO,
                                                   float* __restrict__ out) {
    __shared__ float As[16][132];
    __shared__ float Bs[16][132];
    const int tid = threadIdx.x;
    const int tx = tid & 15, ty = tid >> 4;
    const int rowA = blockIdx.y * 128;
    const int colB = blockIdx.x * 128;
    float acc[8][8];
#pragma unroll
    for (int a = 0; a < 8; a++)
#pragma unroll
        for (int b = 0; b < 8; b++) acc[a][b] = 0.f;

    const int am  = tid >> 2;
    const int akk = (tid & 3) << 2;
    const int bk  = tid >> 5;
    const int bc4 = (tid & 31) << 2;
    const float* Aptr = g_Z + (rowA + am) * HIDDEN + akk;
    const float* Bptr = WO + bk * HIDDEN + colB + bc4;

    float4 pa[2], pb[2];
    pa[0] = *(const float4*)(Aptr);
    pa[1] = *(const float4*)(Aptr + 64 * HIDDEN);
    pb[0] = *(const float4*)(Bptr);
    pb[1] = *(const float4*)(Bptr + 8 * HIDDEN);

    for (int k0 = 0; k0 < HIDDEN; k0 += 16) {
#pragma unroll
        for (int u = 0; u < 2; u++) {
            int m = u * 64 + am;
            As[akk + 0][m] = pa[u].x; As[akk + 1][m] = pa[u].y;
            As[akk + 2][m] = pa[u].z; As[akk + 3][m] = pa[u].w;
            *(float4*)&Bs[u * 8 + bk][bc4] = pb[u];
        }
        __syncthreads();
        if (k0 + 16 < HIDDEN) {
            pa[0] = *(const float4*)(Aptr + k0 + 16);
            pa[1] = *(const float4*)(Aptr + 64 * HIDDEN + k0 + 16);
            pb[0] = *(const float4*)(Bptr + (k0 + 16) * HIDDEN);
            pb[1] = *(const float4*)(Bptr + (k0 + 24) * HIDDEN);
        }
#pragma unroll
        for (int k = 0; k < 16; k++) {
            float ar[8], br[8];
            *(float4*)(ar)     = *(float4*)&As[k][ty * 8];
            *(float4*)(ar + 4) = *(float4*)&As[k][ty * 8 + 4];
            *(float4*)(br)     = *(float4*)&Bs[k][tx * 8];
            *(float4*)(br + 4) = *(float4*)&Bs[k][tx * 8 + 4];
#pragma unroll
            for (int a = 0; a < 8; a++)
#pragma unroll
                for (int b = 0; b < 8; b++) acc[a][b] += ar[a] * br[b];
        }
        __syncthreads();
    }
#pragma unroll
    for (int a = 0; a < 8; a++) {
        int r = rowA + ty * 8 + a;
        float* dst = out + r * HIDDEN + colB + tx * 8;
#pragma unroll
        for (int q = 0; q < 8; q++) dst[q] = acc[a][q];
    }
}

// ---------------- launcher ----------------
extern "C" void kernel_launch(void* const* d_in, const int* in_sizes, int n_in,
                              void* d_out, int out_size) {
    const float* X   = (const float*)d_in[0];
    const float* WQ  = (const float*)d_in[1];
    const float* WK  = (const float*)d_in[2];
    const float* WV  = (const float*)d_in[3];
    const float* WG  = (const float*)d_in[4];
    const float* WO  = (const float*)d_in[5];
    const float* gnw = (const float*)d_in[6];
    const float* gnb = (const float*)d_in[7];
    float* out = (float*)d_out;
    (void)in_sizes; (void)n_in; (void)out_size;

    cudaFuncSetAttribute(retention_intra, cudaFuncAttributeMaxDynamicSharedMemorySize, RET_SMEM_BYTES);

    pack_w<<<(HIDDEN * NQKV + 255) / 256, 256>>>(WQ, WK, WV, WG);
    xpos_tables<<<(Ss * 32 + 255) / 256, 256>>>();
    gemm_proj<<<dim3(NQKV / 128, MROWS / 128), 256>>>(X);
    retention_cross<<<BHN * 4, 256>>>();
    retention_intra<<<dim3(NCHK, BHN), 256, RET_SMEM_BYTES>>>();
    gn_gate<<<dim3(Ss, Bb), 256>>>(gnw, gnb);
    gemm_out<<<dim3(HIDDEN / 128, MROWS / 128), 256>>>(WO, out);
}

// round 9
// speedup vs baseline: 3.4964x; 1.4029x over previous
#include <cuda_runtime.h>
#include <cuda_bf16.h>
#include <stdint.h>
#include <math.h>

// ---------------- fixed problem dimensions ----------------
#define Bb      4
#define Ss      2048
#define HIDDEN  512
#define Hh      8
#define HD      64
#define CHK     64
#define NCHK    32
#define BHN     32
#define MROWS   8192
#define NQKV    2048
#define KSPLIT  1536         // 3 * HIDDEN (bf16 split-K)
#define NCHUNKS 24           // KSPLIT / 64
#define SST     72           // smem row stride (elements), 144B: ldmatrix conflict-free

// ---------------- device scratch ----------------
__device__ __nv_bfloat16 g_Ap[MROWS * KSPLIT];    // [m][k']  = [Ah|Ah|Al]
__device__ __nv_bfloat16 g_Bt[NQKV * KSPLIT];     // [n][k']  = [Bh|Bl|Bh]
__device__ __nv_bfloat16 g_Zp[MROWS * KSPLIT];    // gated/normed Z split
__device__ __nv_bfloat16 g_WOt[HIDDEN * KSPLIT];  // [n][k'] for out GEMM
__device__ float g_Q[BHN * Ss * HD];
__device__ float g_K[BHN * Ss * HD];
__device__ float g_V[BHN * Ss * HD];
__device__ float g_gate[MROWS * HIDDEN];
__device__ float g_Y[BHN * Ss * HD];
__device__ float g_Y2[BHN * Ss * HD];
__device__ float g_sq[Ss * 32];
__device__ float g_cq[Ss * 32];
__device__ float g_sk[Ss * 32];
__device__ float g_ck[Ss * 32];

// ---------------- PTX helpers (sm_80-class: ldmatrix / mma.sync / cp.async) ----------------
__device__ __forceinline__ uint32_t smem_u32(const void* p) {
    uint32_t a;
    asm("{ .reg .u64 t; cvta.to.shared.u64 t, %1; cvt.u32.u64 %0, t; }" : "=r"(a) : "l"(p));
    return a;
}
__device__ __forceinline__ void ldsm_x4(uint32_t& r0, uint32_t& r1, uint32_t& r2, uint32_t& r3,
                                        uint32_t addr) {
    asm volatile("ldmatrix.sync.aligned.m8n8.x4.shared.b16 {%0,%1,%2,%3}, [%4];"
                 : "=r"(r0), "=r"(r1), "=r"(r2), "=r"(r3) : "r"(addr));
}
__device__ __forceinline__ void mma16816(float* d, const uint32_t* a, const uint32_t* b) {
    asm volatile("mma.sync.aligned.m16n8k16.row.col.f32.bf16.bf16.f32 "
                 "{%0,%1,%2,%3}, {%4,%5,%6,%7}, {%8,%9}, {%0,%1,%2,%3};"
                 : "+f"(d[0]), "+f"(d[1]), "+f"(d[2]), "+f"(d[3])
                 : "r"(a[0]), "r"(a[1]), "r"(a[2]), "r"(a[3]), "r"(b[0]), "r"(b[1]));
}
__device__ __forceinline__ void cpasync16(uint32_t dst, const void* src) {
    asm volatile("cp.async.cg.shared.global [%0], [%1], 16;" :: "r"(dst), "l"(src) : "memory");
}
#define CP_COMMIT() asm volatile("cp.async.commit_group;" ::: "memory")
#define CP_WAIT1()  asm volatile("cp.async.wait_group 1;" ::: "memory")
#define CP_WAIT0()  asm volatile("cp.async.wait_group 0;" ::: "memory")

// smem layout (bytes): A buf = 128*SST*2 = 18432; [A0][B0][A1][B1]
#define BUFA_BYTES 18432
#define BUF_BYTES  (2 * BUFA_BYTES)      // 36864 per stage
#define GEMM_SMEM  (2 * BUF_BYTES)       // 73728 total

// ---------------- xPos factor tables ----------------
__global__ void xpos_tables() {
    int idx = blockIdx.x * blockDim.x + threadIdx.x;
    if (idx >= Ss * 32) return;
    int pos = idx >> 5, t = idx & 31;
    float inv_freq = (float)pow(10000.0, -(double)t / 32.0);
    float ang_f = (float)((double)pos * (double)inv_freq);
    double sn = sin((double)ang_f);
    double cs = cos((double)ang_f);
    float sbase = ((float)(2 * t) + 25.6f) / 89.6f;
    float scf = (float)pow((double)sbase, (double)pos / 512.0);
    float snf = (float)sn, csf = (float)cs;
    g_sq[idx] = snf * scf;
    g_cq[idx] = csf * scf;
    float iscf = 1.0f / scf;
    g_sk[idx] = snf * iscf;
    g_ck[idx] = csf * iscf;
}

// ---------------- split conversions ----------------
__device__ __forceinline__ void split_bf16(float x, __nv_bfloat16& h, __nv_bfloat16& l) {
    h = __float2bfloat16(x);
    l = __float2bfloat16(x - __bfloat162float(h));
}

__global__ void conv_x(const float* __restrict__ X) {
    int idx = blockIdx.x * blockDim.x + threadIdx.x;
    if (idx >= MROWS * HIDDEN) return;
    int m = idx >> 9, k = idx & 511;
    __nv_bfloat16 h, l;
    split_bf16(X[idx], h, l);
    size_t base = (size_t)m * KSPLIT;
    g_Ap[base + k] = h;
    g_Ap[base + 512 + k] = h;
    g_Ap[base + 1024 + k] = l;
}

__global__ void conv_w_proj(const float* __restrict__ WQ, const float* __restrict__ WK,
                            const float* __restrict__ WV, const float* __restrict__ WG) {
    int idx = blockIdx.x * blockDim.x + threadIdx.x;
    if (idx >= HIDDEN * NQKV) return;
    int k = idx / NQKV, j = idx - k * NQKV;
    int t = j >> 9, c = j & 511, n = c >> 6, d = c & 63;
    float v;
    if (t == 0)      v = WQ[(n * HIDDEN + k) * HD + d];
    else if (t == 1) v = WK[(n * HIDDEN + k) * HD + d];
    else if (t == 2) v = WV[(n * HIDDEN + k) * HD + d];
    else             v = WG[k * HIDDEN + c];
    __nv_bfloat16 h, l;
    split_bf16(v, h, l);
    size_t base = (size_t)j * KSPLIT;
    g_Bt[base + k] = h;
    g_Bt[base + 512 + k] = l;
    g_Bt[base + 1024 + k] = h;
}

__global__ void conv_wo(const float* __restrict__ WO) {
    int idx = blockIdx.x * blockDim.x + threadIdx.x;
    if (idx >= HIDDEN * HIDDEN) return;
    int k = idx >> 9, n = idx & 511;
    __nv_bfloat16 h, l;
    split_bf16(WO[k * HIDDEN + n], h, l);
    size_t base = (size_t)n * KSPLIT;
    g_WOt[base + k] = h;
    g_WOt[base + 512 + k] = l;
    g_WOt[base + 1024 + k] = h;
}

// ---------------- HMMA bf16-split GEMM mainloop (shared) ----------------
// acc[mt][nt][4] per thread; warp wid: wm=wid>>2 (2), wn=wid&3 (4); warp tile 64x32.
__device__ __forceinline__ void hmma_issue(const __nv_bfloat16* Ag, const __nv_bfloat16* Bg,
                                           uint32_t sb, int i, int b, int tid) {
#pragma unroll
    for (int q = 0; q < 4; q++) {
        int idx = q * 256 + tid;
        int row = idx >> 3;
        int c8  = (idx & 7) * 8;
        uint32_t doff = sb + b * BUF_BYTES + (uint32_t)(row * SST + c8) * 2;
        const __nv_bfloat16* sa = Ag + (size_t)row * KSPLIT + i * 64 + c8;
        const __nv_bfloat16* sb2 = Bg + (size_t)row * KSPLIT + i * 64 + c8;
        cpasync16(doff, sa);
        cpasync16(doff + BUFA_BYTES, sb2);
    }
    CP_COMMIT();
}

__device__ __forceinline__ void hmma_compute(uint32_t sb, int b, int wm, int wn, int lane,
                                             float acc[4][4][4]) {
    const int lrow = lane & 15;
    const int lcol = (lane >> 4) * 8;
    uint32_t aBase = sb + b * BUF_BYTES + (uint32_t)((wm * 64 + lrow) * SST + lcol) * 2;
    uint32_t bBase = sb + b * BUF_BYTES + BUFA_BYTES + (uint32_t)((wn * 32 + lrow) * SST + lcol) * 2;
#pragma unroll
    for (int kk = 0; kk < 4; kk++) {
        uint32_t af[4][4];
#pragma unroll
        for (int mt = 0; mt < 4; mt++)
            ldsm_x4(af[mt][0], af[mt][1], af[mt][2], af[mt][3],
                    aBase + (uint32_t)(mt * 16 * SST + kk * 16) * 2);
        uint32_t bf[4][2];
#pragma unroll
        for (int np = 0; np < 2; np++) {
            uint32_t r0, r1, r2, r3;
            ldsm_x4(r0, r1, r2, r3, bBase + (uint32_t)(np * 16 * SST + kk * 16) * 2);
            bf[np * 2][0] = r0;     bf[np * 2][1] = r2;
            bf[np * 2 + 1][0] = r1; bf[np * 2 + 1][1] = r3;
        }
#pragma unroll
        for (int mt = 0; mt < 4; mt++)
#pragma unroll
            for (int nt = 0; nt < 4; nt++)
                mma16816(acc[mt][nt], af[mt], bf[nt]);
    }
}

__device__ __forceinline__ void hmma_mainloop(const __nv_bfloat16* Ab, const __nv_bfloat16* Bb2,
                                              int rowA, int colB, uint32_t sb,
                                              float acc[4][4][4]) {
    const int tid = threadIdx.x;
    const int wid = tid >> 5, lane = tid & 31;
    const int wm = wid >> 2, wn = wid & 3;
#pragma unroll
    for (int mt = 0; mt < 4; mt++)
#pragma unroll
        for (int nt = 0; nt < 4; nt++)
#pragma unroll
            for (int e = 0; e < 4; e++) acc[mt][nt][e] = 0.f;

    const __nv_bfloat16* Ag = Ab + (size_t)rowA * KSPLIT;
    const __nv_bfloat16* Bg = Bb2 + (size_t)colB * KSPLIT;

    hmma_issue(Ag, Bg, sb, 0, 0, tid);
    for (int i = 0; i < NCHUNKS; i++) {
        if (i + 1 < NCHUNKS) {
            hmma_issue(Ag, Bg, sb, i + 1, (i + 1) & 1, tid);
            CP_WAIT1();
        } else {
            CP_WAIT0();
        }
        __syncthreads();
        hmma_compute(sb, i & 1, wm, wn, lane, acc);
        __syncthreads();
    }
}

// ---------------- projection GEMM (HMMA) + xPos/silu epilogue ----------------
__global__ __launch_bounds__(256, 2) void gemm_proj_tc() {
    extern __shared__ char smem[];
    uint32_t sb = smem_u32(smem);
    const int tid = threadIdx.x;
    const int wid = tid >> 5, lane = tid & 31;
    const int wm = wid >> 2, wn = wid & 3;
    const int rowA = blockIdx.y * 128, colB = blockIdx.x * 128;

    float acc[4][4][4];
    hmma_mainloop(g_Ap, g_Bt, rowA, colB, sb, acc);

#pragma unroll
    for (int nt = 0; nt < 4; nt++) {
        int c = colB + wn * 32 + nt * 8 + (lane & 3) * 2;   // even column
        int t = c >> 9, cc = c & 511, hh = cc >> 6, d0 = cc & 63;
#pragma unroll
        for (int mt = 0; mt < 4; mt++) {
#pragma unroll
            for (int p = 0; p < 2; p++) {
                int r = rowA + wm * 64 + mt * 16 + (lane >> 2) + p * 8;
                int bbv = r >> 11, s = r & 2047;
                float x0 = acc[mt][nt][2 * p], x1 = acc[mt][nt][2 * p + 1];
                if (t <= 1) {
                    const float* stab = (t == 0) ? g_sq : g_sk;
                    const float* ctab = (t == 0) ? g_cq : g_ck;
                    int ti = s * 32 + (d0 >> 1);
                    float sn = stab[ti], cs = ctab[ti];
                    float2 o = make_float2(x0 * cs - x1 * sn, x1 * cs + x0 * sn);
                    float* dst = ((t == 0) ? g_Q : g_K) +
                                 ((size_t)(bbv * Hh + hh) * Ss + s) * HD + d0;
                    *(float2*)dst = o;
                } else if (t == 2) {
                    float* dst = g_V + ((size_t)(bbv * Hh + hh) * Ss + s) * HD + d0;
                    *(float2*)dst = make_float2(x0, x1);
                } else {
                    float* dst = g_gate + (size_t)r * HIDDEN + cc;
                    *(float2*)dst = make_float2(x0 / (1.f + expf(-x0)),
                                                x1 / (1.f + expf(-x1)));
                }
            }
        }
    }
}

// ---------------- output GEMM (HMMA) ----------------
__global__ __launch_bounds__(256, 2) void gemm_out_tc(float* __restrict__ out) {
    extern __shared__ char smem[];
    uint32_t sb = smem_u32(smem);
    const int tid = threadIdx.x;
    const int wid = tid >> 5, lane = tid & 31;
    const int wm = wid >> 2, wn = wid & 3;
    const int rowA = blockIdx.y * 128, colB = blockIdx.x * 128;

    float acc[4][4][4];
    hmma_mainloop(g_Zp, g_WOt, rowA, colB, sb, acc);

#pragma unroll
    for (int mt = 0; mt < 4; mt++)
#pragma unroll
        for (int p = 0; p < 2; p++) {
            int r = rowA + wm * 64 + mt * 16 + (lane >> 2) + p * 8;
#pragma unroll
            for (int nt = 0; nt < 4; nt++) {
                int c = colB + wn * 32 + nt * 8 + (lane & 3) * 2;
                *(float2*)(out + (size_t)r * HIDDEN + c) =
                    make_float2(acc[mt][nt][2 * p], acc[mt][nt][2 * p + 1]);
            }
        }
}

// ---------------- retention intra: diagonal chunk only ----------------
#define RET_SMEM_FLOATS (3 * 64 * 68 + 128)
#define RET_SMEM_BYTES  (RET_SMEM_FLOATS * 4)

__global__ __launch_bounds__(256) void retention_intra() {
    extern __shared__ float sm[];
    float* Qt   = sm;
    float* Kt   = sm + 64 * 68;
    float* Vs   = sm + 2 * 64 * 68;
    float* gpos = sm + 3 * 64 * 68;

    const int qc = blockIdx.x;
    const int bh = blockIdx.y;
    const int h  = bh & 7;
    const int tid = threadIdx.x;
    const int tx = tid & 15, ty = tid >> 4;
    const int i0 = ty * 4, j0 = tx * 4;
    const int rr = tid >> 2;
    const int g4 = (tid & 3) * 4;

    float lg0 = logf(1.0f / 32.0f);
    float lg1 = logf(1.0f / 512.0f);
    float lin = lg0 + (float)h * ((lg1 - lg0) / 7.0f);
    float gamma = 1.0f - expf(lin);
    double gd = (double)gamma;
    if (tid < 64) gpos[tid] = (float)pow(gd, (double)tid);

    const float* Qg = g_Q + ((size_t)bh * Ss + qc * CHK) * HD;
    const float* Kg = g_K + ((size_t)bh * Ss + qc * CHK) * HD;
    const float* Vg = g_V + ((size_t)bh * Ss + qc * CHK) * HD;
#pragma unroll
    for (int u = 0; u < 4; u++) {
        int c4 = g4 + u * 16;
        float4 q = *(const float4*)(Qg + rr * HD + c4);
        Qt[(c4 + 0) * 68 + rr] = q.x;
        Qt[(c4 + 1) * 68 + rr] = q.y;
        Qt[(c4 + 2) * 68 + rr] = q.z;
        Qt[(c4 + 3) * 68 + rr] = q.w;
        float4 k = *(const float4*)(Kg + rr * HD + c4);
        Kt[(c4 + 0) * 68 + rr] = k.x;
        Kt[(c4 + 1) * 68 + rr] = k.y;
        Kt[(c4 + 2) * 68 + rr] = k.z;
        Kt[(c4 + 3) * 68 + rr] = k.w;
        *(float4*)(Vs + rr * 68 + c4) = *(const float4*)(Vg + rr * HD + c4);
    }
    __syncthreads();

    float sv[4][4];
#pragma unroll
    for (int a = 0; a < 4; a++)
#pragma unroll
        for (int b = 0; b < 4; b++) sv[a][b] = 0.f;
#pragma unroll 8
    for (int d = 0; d < 64; d++) {
        float4 qa = *(float4*)(Qt + d * 68 + i0);
        float4 kb = *(float4*)(Kt + d * 68 + j0);
        float aq[4] = {qa.x, qa.y, qa.z, qa.w};
        float bk2[4] = {kb.x, kb.y, kb.z, kb.w};
#pragma unroll
        for (int a = 0; a < 4; a++)
#pragma unroll
            for (int b = 0; b < 4; b++) sv[a][b] += aq[a] * bk2[b];
    }
#pragma unroll
    for (int a = 0; a < 4; a++)
#pragma unroll
        for (int b = 0; b < 4; b++) {
            int e = (i0 + a) - (j0 + b);
            if (e < 0) e = -e;
            sv[a][b] *= gpos[e];
        }
    __syncthreads();
#pragma unroll
    for (int b = 0; b < 4; b++) {
        *(float4*)(Kt + (j0 + b) * 68 + i0) =
            make_float4(sv[0][b], sv[1][b], sv[2][b], sv[3][b]);
    }
    __syncthreads();

    float o[4][4];
#pragma unroll
    for (int a = 0; a < 4; a++)
#pragma unroll
        for (int b = 0; b < 4; b++) o[a][b] = 0.f;
#pragma unroll 8
    for (int j = 0; j < 64; j++) {
        float4 s4 = *(float4*)(Kt + j * 68 + i0);
        float4 vv = *(float4*)(Vs + j * 68 + j0);
        float as[4] = {s4.x, s4.y, s4.z, s4.w};
        float bv[4] = {vv.x, vv.y, vv.z, vv.w};
#pragma unroll
        for (int a = 0; a < 4; a++)
#pragma unroll
            for (int b = 0; b < 4; b++) o[a][b] += as[a] * bv[b];
    }

    float* Yg = g_Y + ((size_t)bh * Ss + qc * CHK) * HD;
#pragma unroll
    for (int a = 0; a < 4; a++)
        *(float4*)(Yg + (i0 + a) * HD + j0) = make_float4(o[a][0], o[a][1], o[a][2], o[a][3]);
}

// ---------------- retention cross: chunked recurrence, register-prefetched ----------------
__global__ __launch_bounds__(256) void retention_cross() {
    __shared__ float Qt[64 * 68];
    __shared__ float Ks[64 * 68];
    __shared__ float Vs[64 * 20];
    __shared__ float Rs[64 * 20];

    const int bh  = blockIdx.x >> 2;
    const int qtr = blockIdx.x & 3;
    const int h   = bh & 7;
    const int tid = threadIdx.x;
    const int tx  = tid & 15, ty = tid >> 4;
    const int i0  = ty * 4;
    const int rr  = tid >> 2;
    const int g4  = (tid & 3) * 4;

    float lg0 = logf(1.0f / 32.0f);
    float lg1 = logf(1.0f / 512.0f);
    float lin = lg0 + (float)h * ((lg1 - lg0) / 7.0f);
    float gamma = 1.0f - expf(lin);
    double gd = (double)gamma;
    const float g64f = (float)pow(gd, 64.0);
    const float gq = (float)pow(gd, (double)rr);
    const float gk = (float)pow(gd, -(double)rr);

    for (int idx = tid; idx < 64 * 20; idx += 256) Rs[idx] = 0.f;

    const float* Qb = g_Q + (size_t)bh * Ss * HD;
    const float* Kb = g_K + (size_t)bh * Ss * HD;
    const float* Vb = g_V + (size_t)bh * Ss * HD;
    float* Yb = g_Y2 + (size_t)bh * Ss * HD;

    float4 pq[4], pk[4], pv;
#pragma unroll
    for (int u = 0; u < 4; u++) {
        int c4 = g4 + u * 16;
        pq[u] = *(const float4*)(Qb + rr * HD + c4);
        pk[u] = *(const float4*)(Kb + rr * HD + c4);
    }
    pv = *(const float4*)(Vb + rr * HD + qtr * 16 + g4);
    __syncthreads();

    for (int qc = 0; qc < NCHK; qc++) {
#pragma unroll
        for (int u = 0; u < 4; u++) {
            int c4 = g4 + u * 16;
            Qt[(c4 + 0) * 68 + rr] = pq[u].x * gq;
            Qt[(c4 + 1) * 68 + rr] = pq[u].y * gq;
            Qt[(c4 + 2) * 68 + rr] = pq[u].z * gq;
            Qt[(c4 + 3) * 68 + rr] = pq[u].w * gq;
            *(float4*)(Ks + rr * 68 + c4) =
                make_float4(pk[u].x * gk, pk[u].y * gk, pk[u].z * gk, pk[u].w * gk);
        }
        *(float4*)(Vs + rr * 20 + g4) = pv;
        __syncthreads();

        if (qc + 1 < NCHK) {
            const float* Qg = Qb + (size_t)(qc + 1) * CHK * HD;
            const float* Kg = Kb + (size_t)(qc + 1) * CHK * HD;
            const float* Vg = Vb + (size_t)(qc + 1) * CHK * HD;
#pragma unroll
            for (int u = 0; u < 4; u++) {
                int c4 = g4 + u * 16;
                pq[u] = *(const float4*)(Qg + rr * HD + c4);
                pk[u] = *(const float4*)(Kg + rr * HD + c4);
            }
            pv = *(const float4*)(Vg + rr * HD + qtr * 16 + g4);
        }

        float o4[4] = {0.f, 0.f, 0.f, 0.f};
#pragma unroll 8
        for (int d = 0; d < 64; d++) {
            float4 q = *(float4*)(Qt + d * 68 + i0);
            float r = Rs[d * 20 + tx];
            o4[0] += q.x * r; o4[1] += q.y * r; o4[2] += q.z * r; o4[3] += q.w * r;
        }
        float* Yo = Yb + (size_t)(qc * CHK + i0) * HD + qtr * 16 + tx;
        Yo[0]      = o4[0];
        Yo[HD]     = o4[1];
        Yo[2 * HD] = o4[2];
        Yo[3 * HD] = o4[3];

        float c4a[4] = {0.f, 0.f, 0.f, 0.f};
#pragma unroll 8
        for (int j = 0; j < 64; j++) {
            float4 kk = *(float4*)(Ks + j * 68 + i0);
            float v = Vs[j * 20 + tx];
            c4a[0] += kk.x * v; c4a[1] += kk.y * v; c4a[2] += kk.z * v; c4a[3] += kk.w * v;
        }
        __syncthreads();
#pragma unroll
        for (int a = 0; a < 4; a++) {
            int off = (i0 + a) * 20 + tx;
            Rs[off] = g64f * (Rs[off] + c4a[a]);
        }
        __syncthreads();
    }
}

// ---------------- groupnorm + gate, emits bf16 split Z directly ----------------
__global__ __launch_bounds__(256) void gn_gate(const float* __restrict__ gnw,
                                               const float* __restrict__ gnb) {
    int s = blockIdx.x, b = blockIdx.y;
    int tid = threadIdx.x;
    int h = tid >> 5, lane = tid & 31;
    const float* Yg  = g_Y  + ((size_t)(b * Hh + h) * Ss + s) * HD;
    const float* Y2g = g_Y2 + ((size_t)(b * Hh + h) * Ss + s) * HD;
    float y0 = Yg[lane]      + Y2g[lane];
    float y1 = Yg[lane + 32] + Y2g[lane + 32];
    float sum = y0 + y1, sq = y0 * y0 + y1 * y1;
#pragma unroll
    for (int off = 16; off; off >>= 1) {
        sum += __shfl_xor_sync(0xffffffffu, sum, off);
        sq  += __shfl_xor_sync(0xffffffffu, sq,  off);
    }
    float mu = sum * (1.f / 64.f);
    float var = sq * (1.f / 64.f) - mu * mu;
    float rstd = rsqrtf(var + 1e-5f);
    int r = b * Ss + s;
    int c0 = h * 64 + lane;
    float z0 = ((y0 - mu) * rstd * gnw[c0]      + gnb[c0])      * g_gate[(size_t)r * HIDDEN + c0];
    float z1 = ((y1 - mu) * rstd * gnw[c0 + 32] + gnb[c0 + 32]) * g_gate[(size_t)r * HIDDEN + c0 + 32];
    size_t base = (size_t)r * KSPLIT;
    __nv_bfloat16 h0, l0, h1, l1;
    split_bf16(z0, h0, l0);
    split_bf16(z1, h1, l1);
    g_Zp[base + c0]             = h0;
    g_Zp[base + 512 + c0]       = h0;
    g_Zp[base + 1024 + c0]      = l0;
    g_Zp[base + c0 + 32]        = h1;
    g_Zp[base + 512 + c0 + 32]  = h1;
    g_Zp[base + 1024 + c0 + 32] = l1;
}

// ---------------- launcher ----------------
extern "C" void kernel_launch(void* const* d_in, const int* in_sizes, int n_in,
                              void* d_out, int out_size) {
    const float* X   = (const float*)d_in[0];
    const float* WQ  = (const float*)d_in[1];
    const float* WK  = (const float*)d_in[2];
    const float* WV  = (const float*)d_in[3];
    const float* WG  = (const float*)d_in[4];
    const float* WO  = (const float*)d_in[5];
    const float* gnw = (const float*)d_in[6];
    const float* gnb = (const float*)d_in[7];
    float* out = (float*)d_out;
    (void)in_sizes; (void)n_in; (void)out_size;

    cudaFuncSetAttribute(retention_intra, cudaFuncAttributeMaxDynamicSharedMemorySize, RET_SMEM_BYTES);
    cudaFuncSetAttribute(gemm_proj_tc, cudaFuncAttributeMaxDynamicSharedMemorySize, GEMM_SMEM);
    cudaFuncSetAttribute(gemm_out_tc, cudaFuncAttributeMaxDynamicSharedMemorySize, GEMM_SMEM);

    xpos_tables<<<(Ss * 32 + 255) / 256, 256>>>();
    conv_w_proj<<<(HIDDEN * NQKV + 255) / 256, 256>>>(WQ, WK, WV, WG);
    conv_wo<<<(HIDDEN * HIDDEN + 255) / 256, 256>>>(WO);
    conv_x<<<(MROWS * HIDDEN + 255) / 256, 256>>>(X);
    gemm_proj_tc<<<dim3(NQKV / 128, MROWS / 128), 256, GEMM_SMEM>>>();
    retention_cross<<<BHN * 4, 256>>>();
    retention_intra<<<dim3(NCHK, BHN), 256, RET_SMEM_BYTES>>>();
    gn_gate<<<dim3(Ss, Bb), 256>>>(gnw, gnb);
    gemm_out_tc<<<dim3(HIDDEN / 128, MROWS / 128), 256, GEMM_SMEM>>>(out);
}